// round 13
// baseline (speedup 1.0000x reference)
#include <cuda_runtime.h>
#include <cuda_fp16.h>
#include <math.h>

#define LMAX 557056       // >= L + 2*rs so 2-deep unguarded prefetch is in-bounds
#define NBS  444          // step grid (3 blocks x 148 SMs, one wave)
#define NTB  256          // step block
#define NBC  592          // convert grid
#define NTC  256          // convert block
#define ESHIFT 6.0f
#define LG2E 1.44269504f

// fp16 copy of z_past: [LMAX][32] halves (16B-aligned; zero tail)
__device__ __align__(16) __half g_zh[(size_t)LMAX * 32];
// per-block partials: [block][132]  (c<4: s_h, c=4+h*32+i: S_h[i])
__device__ float  g_part[NBS * 132];
__device__ float  g_z[32];
__device__ float  g_uf[4][32];     // fp32 u (epilogue correction, natural scale)
__device__ __half2 g_uh[4][16];    // half2 u * log2(e) (mainloop scores)
__device__ float  g_f[4][64];      // correction factors for rows l<64
__device__ unsigned int g_cnt = 0;

// ---------------- scalar-only helpers (no address-taken arrays) -------------
__device__ __forceinline__ __half2 u2h2(unsigned u) {
    __half2 h = *reinterpret_cast<__half2*>(&u); return h;
}
__device__ __forceinline__ unsigned h2u(__half2 h) {
    return *reinterpret_cast<unsigned*>(&h);
}
__device__ __forceinline__ __half2 h2shfl_xor(__half2 v, int o) {
    unsigned u = h2u(v);
    u = __shfl_xor_sync(0xffffffffu, u, o);
    return u2h2(u);
}
__device__ __forceinline__ __half2 h2ex2(__half2 x) {
    unsigned xi = h2u(x), ri;
    asm("ex2.approx.f16x2 %0,%1;" : "=r"(ri) : "r"(xi));
    return u2h2(ri);
}
__device__ __forceinline__ unsigned long long pol_evict_last() {
    unsigned long long p;
    asm("createpolicy.fractional.L2::evict_last.b64 %0, 1.0;" : "=l"(p));
    return p;
}
__device__ __forceinline__ unsigned long long pol_evict_first() {
    unsigned long long p;
    asm("createpolicy.fractional.L2::evict_first.b64 %0, 1.0;" : "=l"(p));
    return p;
}
__device__ __forceinline__ void ldg128h(unsigned& a, unsigned& b, unsigned& c, unsigned& d,
                                        const void* p, unsigned long long pol) {
    asm("ld.global.nc.L2::cache_hint.v4.u32 {%0,%1,%2,%3},[%4],%5;"
        : "=r"(a), "=r"(b), "=r"(c), "=r"(d) : "l"(p), "l"(pol));
}
__device__ __forceinline__ float4 ldg128f(const void* p, unsigned long long pol) {
    float4 v;
    asm("ld.global.nc.L2::cache_hint.v4.f32 {%0,%1,%2,%3},[%4],%5;"
        : "=f"(v.x), "=f"(v.y), "=f"(v.z), "=f"(v.w) : "l"(p), "l"(pol));
    return v;
}
__device__ __forceinline__ void stg128(void* p, int4 v, unsigned long long pol) {
    asm("st.global.L2::cache_hint.v4.b32 [%0],{%1,%2,%3,%4},%5;"
        :: "l"(p), "r"(v.x), "r"(v.y), "r"(v.z), "r"(v.w), "l"(pol) : "memory");
}

// ---- from smem sq (=0.5*q) compute u (g_uf natural, g_uh *log2e) and f (g_f)
__device__ __forceinline__ void compute_u_f(const float* sq, float (*su)[32],
                                            const float* k_w, const float* rbias,
                                            int off, int tid, int nthreads)
{
    if (tid < 128) {
        int h = tid >> 5, i = tid & 31;
        float u = 0.f;
#pragma unroll
        for (int j = 0; j < 8; j++) u += sq[8*h + j] * k_w[(8*h + j) * 32 + i];
        g_uf[h][i] = u;
        su[h][i] = u;
    }
    __syncthreads();
    if (tid < 64) {
        int h = tid >> 4, m = tid & 15;
        g_uh[h][m] = __floats2half2_rn(su[h][2*m] * LG2E, su[h][2*m+1] * LG2E);
    }
    for (int task = tid; task < 256; task += nthreads) {
        int h = task >> 6, l = task & 63;
        int idx = off + l;
        idx = idx < 0 ? 0 : (idx > 128 ? 128 : idx);
        float d = 0.f;
#pragma unroll
        for (int j = 0; j < 8; j++)
            d += sq[8*h + j] * (rbias[idx * 32 + 8*h + j] - rbias[128 * 32 + 8*h + j]);
        g_f[h][l] = __expf(d);
    }
}

// ---------------- convert: z_past -> fp16 (L2-resident), + step-0 init ------
__global__ __launch_bounds__(NTC)
void k_convert(const float* __restrict__ zp, int L,
               const float* __restrict__ cand,
               const float* __restrict__ q_w, const float* __restrict__ q_b,
               const float* __restrict__ k_w, const float* __restrict__ rbias,
               const int* __restrict__ pos)
{
    if (blockIdx.x == 0) {
        __shared__ float scand[32], sq[32], su[4][32];
        int tid = threadIdx.x;
        if (tid < 32) { scand[tid] = cand[tid]; g_z[tid] = cand[tid]; }
        __syncthreads();
        if (tid < 32) {
            float qq = q_b[tid];
#pragma unroll
            for (int i = 0; i < 32; i++) qq += scand[i] * q_w[tid * 32 + i];
            sq[tid] = 0.5f * qq;
        }
        __syncthreads();
        compute_u_f(sq, su, k_w, rbias, pos[0] - L + 64, tid, NTC);
        __syncthreads();
    }
    const unsigned long long pf = pol_evict_first();
    const unsigned long long pl = pol_evict_last();
    const int stride = gridDim.x * blockDim.x;
    for (int l = blockIdx.x * blockDim.x + threadIdx.x; l < LMAX; l += stride) {
        int4 o0, o1, o2, o3;
        if (l < L) {
            const char* row = (const char*)zp + (size_t)l * 128;
            float4 t0 = ldg128f(row,      pf);
            float4 t1 = ldg128f(row + 16, pf);
            float4 t2 = ldg128f(row + 32, pf);
            float4 t3 = ldg128f(row + 48, pf);
            float4 t4 = ldg128f(row + 64, pf);
            float4 t5 = ldg128f(row + 80, pf);
            float4 t6 = ldg128f(row + 96, pf);
            float4 t7 = ldg128f(row + 112, pf);
            o0.x = h2u(__floats2half2_rn(t0.x, t0.y)); o0.y = h2u(__floats2half2_rn(t0.z, t0.w));
            o0.z = h2u(__floats2half2_rn(t1.x, t1.y)); o0.w = h2u(__floats2half2_rn(t1.z, t1.w));
            o1.x = h2u(__floats2half2_rn(t2.x, t2.y)); o1.y = h2u(__floats2half2_rn(t2.z, t2.w));
            o1.z = h2u(__floats2half2_rn(t3.x, t3.y)); o1.w = h2u(__floats2half2_rn(t3.z, t3.w));
            o2.x = h2u(__floats2half2_rn(t4.x, t4.y)); o2.y = h2u(__floats2half2_rn(t4.z, t4.w));
            o2.z = h2u(__floats2half2_rn(t5.x, t5.y)); o2.w = h2u(__floats2half2_rn(t5.z, t5.w));
            o3.x = h2u(__floats2half2_rn(t6.x, t6.y)); o3.y = h2u(__floats2half2_rn(t6.z, t6.w));
            o3.z = h2u(__floats2half2_rn(t7.x, t7.y)); o3.w = h2u(__floats2half2_rn(t7.z, t7.w));
        } else {
            o0 = make_int4(0,0,0,0); o1 = o0; o2 = o0; o3 = o0;   // zero tail
        }
        char* dst = (char*)g_zh + (size_t)l * 64;
        stg128(dst,      o0, pl);
        stg128(dst + 16, o1, pl);
        stg128(dst + 32, o2, pl);
        stg128(dst + 48, o3, pl);
    }
}

#define PROCESS(r0, r1, r2, r3) do { \
    __half2 z0 = u2h2(r0), z1 = u2h2(r1), z2 = u2h2(r2), z3 = u2h2(r3); \
    __half2 p0 = __hmul2(z0, uh0[0]); \
    __half2 p1 = __hmul2(z0, uh1[0]); \
    __half2 p2 = __hmul2(z0, uh2[0]); \
    __half2 p3 = __hmul2(z0, uh3[0]); \
    p0 = __hfma2(z1, uh0[1], p0); p1 = __hfma2(z1, uh1[1], p1); \
    p2 = __hfma2(z1, uh2[1], p2); p3 = __hfma2(z1, uh3[1], p3); \
    p0 = __hfma2(z2, uh0[2], p0); p1 = __hfma2(z2, uh1[2], p1); \
    p2 = __hfma2(z2, uh2[2], p2); p3 = __hfma2(z2, uh3[2], p3); \
    p0 = __hfma2(z3, uh0[3], p0); p1 = __hfma2(z3, uh1[3], p1); \
    p2 = __hfma2(z3, uh2[3], p2); p3 = __hfma2(z3, uh3[3], p3); \
    __half2 q01 = __hadd2(__lows2half2(p0, p1), __highs2half2(p0, p1)); \
    __half2 q23 = __hadd2(__lows2half2(p2, p3), __highs2half2(p2, p3)); \
    q01 = __hadd2(q01, h2shfl_xor(q01, 1)); \
    q23 = __hadd2(q23, h2shfl_xor(q23, 1)); \
    q01 = __hadd2(q01, h2shfl_xor(q01, 2)); \
    q23 = __hadd2(q23, h2shfl_xor(q23, 2)); \
    q01 = __hadd2(q01, ebias); \
    q23 = __hadd2(q23, ebias); \
    __half2 e01 = h2ex2(q01); \
    __half2 e23 = h2ex2(q23); \
    float2 f01 = __half22float2(e01), f23 = __half22float2(e23); \
    s0 += f01.x; s1 += f01.y; s2 += f23.x; s3 += f23.y; \
    __half2 e0 = __low2half2(e01), e1 = __high2half2(e01); \
    __half2 e2 = __low2half2(e23), e3 = __high2half2(e23); \
    a0[0] = __hfma2(e0, z0, a0[0]); a1[0] = __hfma2(e1, z0, a1[0]); \
    a2[0] = __hfma2(e2, z0, a2[0]); a3[0] = __hfma2(e3, z0, a3[0]); \
    a0[1] = __hfma2(e0, z1, a0[1]); a1[1] = __hfma2(e1, z1, a1[1]); \
    a2[1] = __hfma2(e2, z1, a2[1]); a3[1] = __hfma2(e3, z1, a3[1]); \
    a0[2] = __hfma2(e0, z2, a0[2]); a1[2] = __hfma2(e1, z2, a1[2]); \
    a2[2] = __hfma2(e2, z2, a2[2]); a3[2] = __hfma2(e3, z2, a3[2]); \
    a0[3] = __hfma2(e0, z3, a0[3]); a1[3] = __hfma2(e1, z3, a1[3]); \
    a2[3] = __hfma2(e2, z3, a2[3]); a3[3] = __hfma2(e3, z3, a3[3]); \
} while (0)

// ---------------- fused step: quad-per-row, 2-deep pipeline, fused epilogue -
__global__ __launch_bounds__(NTB, 3)
void k_step(int L,
            const float* __restrict__ k_w,
            const float* __restrict__ v_w, const float* __restrict__ v_b,
            const float* __restrict__ o_w, const float* __restrict__ o_b,
            const float* __restrict__ q_w, const float* __restrict__ q_b,
            const float* __restrict__ rbias,
            const float* __restrict__ coupling,
            const float* __restrict__ norm_scale,
            const int* __restrict__ pos,
            float* __restrict__ outp, int last)
{
    const int tid  = threadIdx.x;
    const int gtid = blockIdx.x * NTB + tid;
    const int qg   = gtid & 3;          // quad lane -> component group [8q..8q+8)
    const int lane = tid & 31;
    const int w    = tid >> 5;

    __half2 uh0[4], uh1[4], uh2[4], uh3[4];
#pragma unroll
    for (int m = 0; m < 4; m++) {
        uh0[m] = g_uh[0][qg * 4 + m];
        uh1[m] = g_uh[1][qg * 4 + m];
        uh2[m] = g_uh[2][qg * 4 + m];
        uh3[m] = g_uh[3][qg * 4 + m];
    }
    const __half2 ebias = __float2half2_rn(-ESHIFT * LG2E);

    float s0 = 0.f, s1 = 0.f, s2 = 0.f, s3 = 0.f;
    __half2 a0[4], a1[4], a2[4], a3[4];
#pragma unroll
    for (int m = 0; m < 4; m++) {
        a0[m] = __floats2half2_rn(0.f, 0.f); a1[m] = a0[m];
        a2[m] = a0[m]; a3[m] = a0[m];
    }

    const int rs = (NBS * NTB) >> 2;                 // 28416 rows
    const size_t RSB = (size_t)rs * 64;
    const unsigned long long pl = pol_evict_last();
    const char* p    = (const char*)g_zh + qg * 16 + (size_t)(gtid >> 2) * 64;
    const char* pend = (const char*)g_zh + qg * 16 + (size_t)L * 64;

    unsigned A0, A1, A2, A3, B0, B1, B2, B3;
    ldg128h(A0, A1, A2, A3, p, pl);
    ldg128h(B0, B1, B2, B3, p + RSB, pl);

    while (p < pend) {
        unsigned C0, C1, C2, C3;
        ldg128h(C0, C1, C2, C3, p + 2 * RSB, pl);    // unguarded: tail zero
        PROCESS(A0, A1, A2, A3);
        A0 = B0; A1 = B1; A2 = B2; A3 = B3;
        B0 = C0; B1 = C1; B2 = C2; B3 = C3;
        p += RSB;
    }

    // warp reduction over quads (offsets 4,8,16); lane q keeps group q
#pragma unroll
    for (int o = 4; o <= 16; o <<= 1) {
        s0 += __shfl_xor_sync(0xffffffffu, s0, o);
        s1 += __shfl_xor_sync(0xffffffffu, s1, o);
        s2 += __shfl_xor_sync(0xffffffffu, s2, o);
        s3 += __shfl_xor_sync(0xffffffffu, s3, o);
#pragma unroll
        for (int m = 0; m < 4; m++) {
            a0[m] = __hadd2(a0[m], h2shfl_xor(a0[m], o));
            a1[m] = __hadd2(a1[m], h2shfl_xor(a1[m], o));
            a2[m] = __hadd2(a2[m], h2shfl_xor(a2[m], o));
            a3[m] = __hadd2(a3[m], h2shfl_xor(a3[m], o));
        }
    }

    __shared__ float sm_s[NTB / 32][4];
    __shared__ float sm_S[NTB / 32][4][32];
    if (lane < 4) {
#pragma unroll
        for (int m = 0; m < 4; m++) {
            float2 f;
            f = __half22float2(a0[m]);
            sm_S[w][0][qg * 8 + 2*m] = f.x; sm_S[w][0][qg * 8 + 2*m + 1] = f.y;
            f = __half22float2(a1[m]);
            sm_S[w][1][qg * 8 + 2*m] = f.x; sm_S[w][1][qg * 8 + 2*m + 1] = f.y;
            f = __half22float2(a2[m]);
            sm_S[w][2][qg * 8 + 2*m] = f.x; sm_S[w][2][qg * 8 + 2*m + 1] = f.y;
            f = __half22float2(a3[m]);
            sm_S[w][3][qg * 8 + 2*m] = f.x; sm_S[w][3][qg * 8 + 2*m + 1] = f.y;
        }
        if (lane == 0) {
            sm_s[w][0] = s0; sm_s[w][1] = s1; sm_s[w][2] = s2; sm_s[w][3] = s3;
        }
    }
    __syncthreads();
    for (int c = tid; c < 132; c += NTB) {
        float r2 = 0.f;
        if (c < 4) {
#pragma unroll
            for (int ww = 0; ww < NTB / 32; ww++) r2 += sm_s[ww][c];
        } else {
            int h = (c - 4) >> 5, i = (c - 4) & 31;
#pragma unroll
            for (int ww = 0; ww < NTB / 32; ww++) r2 += sm_S[ww][h][i];
        }
        g_part[blockIdx.x * 132 + c] = r2;
    }

    // ---- last-block epilogue ----
    __shared__ bool amLast;
    __threadfence();
    if (tid == 0) {
        unsigned int v = atomicAdd(&g_cnt, 1u);
        amLast = (v == (unsigned int)(gridDim.x - 1));
    }
    __syncthreads();
    if (!amLast) return;

    __shared__ float red[132];
    {   // warp-parallel partial reduction (lane-strided, high MLP)
        for (int c = w; c < 132; c += NTB / 32) {
            float rr = 0.f;
            for (int b = lane; b < NBS; b += 32) rr += g_part[b * 132 + c];
#pragma unroll
            for (int o = 16; o; o >>= 1) rr += __shfl_down_sync(0xffffffffu, rr, o);
            if (lane == 0) red[c] = rr;
        }
    }
    // first 64 rows of z (rel-bias correction region)
    __shared__ __align__(16) __half szh[64 * 32];
    for (int t = tid; t < 256; t += NTB)
        ((int4*)szh)[t] = ((const int4*)g_zh)[t];
    __shared__ float sw[4][64];
    __syncthreads();

    for (int task = tid; task < 256; task += NTB) {
        int h = task >> 6, l = task & 63;
        float sc = 0.f;
#pragma unroll
        for (int i = 0; i < 32; i++) sc += g_uf[h][i] * __half2float(szh[l * 32 + i]);
        sw[h][l] = (g_f[h][l] - 1.f) * __expf(sc - ESHIFT);   // same shift as mainloop
    }
    __syncthreads();
    if (tid < 128) {
        int h = tid >> 5, i = tid & 31;
        float d = 0.f;
#pragma unroll
        for (int l = 0; l < 64; l++) d += sw[h][l] * __half2float(szh[l * 32 + i]);
        red[4 + h * 32 + i] += d;
        if (tid < 4) {
            float ds = 0.f;
#pragma unroll
            for (int l = 0; l < 64; l++) ds += sw[tid][l];
            red[tid] += ds;
        }
    }
    __syncthreads();

    __shared__ float sout[32], szl[32], sq[32], su[4][32];
    if (tid < 32) {
        int h = tid >> 3;
        float inv = 1.f / red[h];
        float o = v_b[tid];
#pragma unroll
        for (int i = 0; i < 32; i++) o += v_w[tid * 32 + i] * (red[4 + h * 32 + i] * inv);
        sout[tid] = o;
    }
    __syncthreads();
    if (tid < 32) {
        float m = o_b[tid];
#pragma unroll
        for (int i = 0; i < 32; i++) m += sout[i] * o_w[tid * 32 + i];
        float zz = g_z[tid] + coupling[0] * m;
        float sp = (zz > 15.f) ? zz : log1pf(__expf(zz));
        szl[tid] = zz * tanhf(sp);
    }
    __syncthreads();
    if (tid < 32) {
        int pbit = tid & 1;
        float mn = 0.f;
#pragma unroll
        for (int d = 0; d < 16; d++) mn += szl[2 * d + pbit];
        mn *= (1.f / 16.f);
        float var = 0.f;
#pragma unroll
        for (int d = 0; d < 16; d++) { float dd = szl[2 * d + pbit] - mn; var += dd * dd; }
        var *= (1.f / 16.f);
        float zn = (szl[tid] - mn) * rsqrtf(var + 1e-5f) * norm_scale[0];
        g_z[tid] = zn;
        sout[tid] = zn;
        if (last) outp[tid] = zn;
    }
    __syncthreads();
    if (tid < 32) {
        float qq = q_b[tid];
#pragma unroll
        for (int i = 0; i < 32; i++) qq += sout[i] * q_w[tid * 32 + i];
        sq[tid] = 0.5f * qq;
    }
    __syncthreads();
    compute_u_f(sq, su, k_w, rbias, pos[0] - L + 64, tid, NTB);
    if (tid == 0) g_cnt = 0;
}

extern "C" void kernel_launch(void* const* d_in, const int* in_sizes, int n_in,
                              void* d_out, int out_size)
{
    const float* cand   = (const float*)d_in[0];
    const float* zp     = (const float*)d_in[1];
    const float* q_w    = (const float*)d_in[2];
    const float* q_b    = (const float*)d_in[3];
    const float* k_w    = (const float*)d_in[4];
    const float* v_w    = (const float*)d_in[6];
    const float* v_b    = (const float*)d_in[7];
    const float* o_w    = (const float*)d_in[8];
    const float* o_b    = (const float*)d_in[9];
    const float* rbias  = (const float*)d_in[10];
    const float* coup   = (const float*)d_in[11];
    const float* nscale = (const float*)d_in[12];
    const int*   pos    = (const int*)  d_in[13];

    int L = in_sizes[1] / 32;
    float* outp = (float*)d_out;

    k_convert<<<NBC, NTC>>>(zp, L, cand, q_w, q_b, k_w, rbias, pos);
    for (int s = 0; s < 8; s++)
        k_step<<<NBS, NTB>>>(L, k_w, v_w, v_b, o_w, o_b, q_w, q_b,
                             rbias, coup, nscale, pos, outp, s == 7);
}